// round 15
// baseline (speedup 1.0000x reference)
#include <cuda_runtime.h>
#include <math.h>
#include <cstdint>

#define T_LEN     1048576
#define MAXO      25
#define CLAMP_HI  24.0f
#define SEG       4
#define NTHREADS  256
#define NWARP     (NTHREADS/32)
#define PER_BLOCK (SEG*NTHREADS)       /* 1024 */
#define NB        (T_LEN/PER_BLOCK)    /* 1024 tiles */
#define K1_THREADS 512
#define K1_ELEMS   16
#define K1_BLOCKS  (T_LEN/(K1_THREADS*K1_ELEMS))        /* 128 */
#define TILES_PER_K1 ((K1_THREADS*K1_ELEMS)/PER_BLOCK)  /* 8 */
#define FPT       (NB/NTHREADS)        /* 4 fns per thread in global scan */
#define GROUP     128                  /* rows & threads per drain group */
#define FULLM     0xffffffffu

struct Fn { float a, b, c; };

__device__ Fn g_blockF[NB];

__device__ __forceinline__ Fn fn_identity() { return Fn{0.f, -1e30f, 1e30f}; }

// f1 applied first, then f2:  (f2 o f1)(x) = min(max(x+a, b), c)
__device__ __forceinline__ Fn fn_compose(Fn f1, Fn f2) {
    Fn r;
    r.a = f1.a + f2.a;
    r.b = fmaxf(f1.b + f2.a, f2.b);
    r.c = fminf(fmaxf(f1.c + f2.a, f2.b), f2.c);
    return r;
}

__device__ __forceinline__ float fn_apply(Fn f, float x) {
    return fminf(fmaxf(x + f.a, f.b), f.c);
}

__device__ __forceinline__ Fn warp_incl_scan(Fn v, int lane) {
    #pragma unroll
    for (int off = 1; off < 32; off <<= 1) {
        float pa = __shfl_up_sync(FULLM, v.a, off);
        float pb = __shfl_up_sync(FULLM, v.b, off);
        float pc = __shfl_up_sync(FULLM, v.c, off);
        if (lane >= off) v = fn_compose(Fn{pa, pb, pc}, v);
    }
    return v;
}

__device__ __forceinline__ uint32_t smem_u32(const void* p) {
    uint32_t a;
    asm("{ .reg .u64 t; cvta.to.shared.u64 t, %1; cvt.u32.u64 %0, t; }"
        : "=r"(a) : "l"(p));
    return a;
}

// ---------------------------------------------------------------------------
// K1: 128 blocks x 512 threads, 16 elems/thread -> 8 tile functions per block
// ---------------------------------------------------------------------------
__global__ void __launch_bounds__(K1_THREADS)
k1_block_totals(const int* __restrict__ seq, const float* __restrict__ delta) {
    asm volatile("griddepcontrol.launch_dependents;" ::: "memory");

    __shared__ float dl[16];
    __shared__ Fn warpTot[K1_THREADS / 32];   // 16
    int tid = threadIdx.x, lane = tid & 31, wid = tid >> 5;
    if (tid < 16) dl[tid] = delta[tid];
    __syncthreads();

    const int4* p = (const int4*)(seq + (size_t)blockIdx.x * (K1_THREADS * K1_ELEMS)
                                      + tid * K1_ELEMS);
    int4 w0 = p[0], w1 = p[1], w2 = p[2], w3 = p[3];
    int vals[16] = {w0.x, w0.y, w0.z, w0.w, w1.x, w1.y, w1.z, w1.w,
                    w2.x, w2.y, w2.z, w2.w, w3.x, w3.y, w3.z, w3.w};

    Fn f = fn_identity();
    #pragma unroll
    for (int i = 0; i < 16; i++) {
        float d = dl[vals[i]];
        f.a += d;
        f.b = fmaxf(f.b + d, 0.f);
        f.c = fminf(fmaxf(f.c + d, 0.f), CLAMP_HI);
    }
    Fn inc = warp_incl_scan(f, lane);
    if (lane == 31) warpTot[wid] = inc;
    __syncthreads();
    if (tid < TILES_PER_K1) {
        Fn t = fn_compose(warpTot[tid * 2], warpTot[tid * 2 + 1]);
        g_blockF[blockIdx.x * TILES_PER_K1 + tid] = t;
    }
}

// ---------------------------------------------------------------------------
// K3: R7 scan structure + scalar tables; output drained by TWO independent
//     128-thread groups, each with its own 12.8 KB staging half and its own
//     cp.async.bulk chain (double-buffered drain, same SMEM footprint).
// ---------------------------------------------------------------------------
__global__ void __launch_bounds__(NTHREADS)
k3_output(const int* __restrict__ seq, const float* __restrict__ delta,
          const float* __restrict__ bias, const float* __restrict__ scale,
          float* __restrict__ out) {
    __shared__ float dl[16];
    __shared__ float An[MAXO], Ap[MAXO];
    __shared__ float SufAn[MAXO + 1], PreAp[MAXO + 1];
    __shared__ Fn    warpTotG[NWARP];
    __shared__ Fn    warpTot[NWARP];
    __shared__ float s_start;
    __shared__ __align__(16) float cnt[NTHREADS * (SEG + 1)];   // 5.1 KB
    __shared__ __align__(16) float stage[NTHREADS * MAXO];      // 2 x 12.8 KB

    int tid = threadIdx.x, lane = tid & 31, wid = tid >> 5, bid = blockIdx.x;
    float s = scale[0];
    if (tid < 16) dl[tid] = delta[tid];
    if (tid < MAXO) {
        float fj = (float)tid;
        An[tid] = expf(bias[tid] - s * fj);   // j >= c path (* e^{ s c})
        Ap[tid] = expf(bias[tid] + s * fj);   // j <  c path (* e^{-s c})
    }

    // issue seq loads early
    const int4* p = (const int4*)(seq + (size_t)bid * PER_BLOCK + tid * SEG);
    int4 v0 = p[0];

    // K1's tile functions must be visible past this point (PDL)
    asm volatile("griddepcontrol.wait;" ::: "memory");

    // load this thread's FPT=4 global tile functions (L2-hot)
    Fn g4[FPT];
    #pragma unroll
    for (int i = 0; i < FPT; i++) g4[i] = g_blockF[FPT * tid + i];
    __syncthreads();

    if (tid == 0) {
        float a = 0.f;
        SufAn[MAXO] = 0.f;
        for (int k = MAXO - 1; k >= 0; k--) { a += An[k]; SufAn[k] = a; }
    }
    if (tid == 32) {
        float a = 0.f;
        PreAp[0] = 0.f;
        for (int k = 1; k <= MAXO; k++) { a += Ap[k - 1]; PreAp[k] = a; }
    }

    // ---- block-wide scan over the 1024 tile functions (4 per thread) ----
    Fn quad = g4[0];
    #pragma unroll
    for (int i = 1; i < FPT; i++) quad = fn_compose(quad, g4[i]);
    Fn incG = warp_incl_scan(quad, lane);
    if (lane == 31) warpTotG[wid] = incG;
    __syncthreads();
    if (wid == 0) {
        Fn v = (lane < NWARP) ? warpTotG[lane] : fn_identity();
        #pragma unroll
        for (int off = 1; off < NWARP; off <<= 1) {
            float pa = __shfl_up_sync(FULLM, v.a, off);
            float pb = __shfl_up_sync(FULLM, v.b, off);
            float pc = __shfl_up_sync(FULLM, v.c, off);
            if (lane >= off) v = fn_compose(Fn{pa, pb, pc}, v);
        }
        if (lane < NWARP) warpTotG[lane] = v;
    }
    __syncthreads();
    {
        float pa = __shfl_up_sync(FULLM, incG.a, 1);
        float pb = __shfl_up_sync(FULLM, incG.b, 1);
        float pc = __shfl_up_sync(FULLM, incG.c, 1);
        Fn lane_excl = (lane == 0) ? fn_identity() : Fn{pa, pb, pc};
        Fn wexcl     = (wid  == 0) ? fn_identity() : warpTotG[wid - 1];
        Fn exclG = fn_compose(wexcl, lane_excl);   // prefix of fns [0, FPT*tid)
        if (tid == (bid >> 2)) {
            Fn e = exclG;
            #pragma unroll
            for (int i = 0; i < FPT - 1; i++)
                if (i < (bid & 3)) e = fn_compose(e, g4[i]);
            s_start = fn_apply(e, 0.f);
        }
    }

    // ---- per-thread fn over its 4 symbols ----
    int vals[SEG] = {v0.x, v0.y, v0.z, v0.w};
    float dv[SEG];
    Fn f = fn_identity();
    #pragma unroll
    for (int i = 0; i < SEG; i++) {
        float d = dl[vals[i]];
        dv[i] = d;
        f.a += d;
        f.b = fmaxf(f.b + d, 0.f);
        f.c = fminf(fmaxf(f.c + d, 0.f), CLAMP_HI);
    }

    // ---- block scan of thread functions ----
    Fn inc = warp_incl_scan(f, lane);
    if (lane == 31) warpTot[wid] = inc;
    __syncthreads();                                // also publishes s_start
    if (wid == 0) {
        Fn v = (lane < NWARP) ? warpTot[lane] : fn_identity();
        #pragma unroll
        for (int off = 1; off < NWARP; off <<= 1) {
            float pa = __shfl_up_sync(FULLM, v.a, off);
            float pb = __shfl_up_sync(FULLM, v.b, off);
            float pc = __shfl_up_sync(FULLM, v.c, off);
            if (lane >= off) v = fn_compose(Fn{pa, pb, pc}, v);
        }
        if (lane < NWARP) warpTot[lane] = v;
    }
    __syncthreads();
    float pa = __shfl_up_sync(FULLM, inc.a, 1);
    float pb = __shfl_up_sync(FULLM, inc.b, 1);
    float pc = __shfl_up_sync(FULLM, inc.c, 1);
    Fn lane_excl = (lane == 0) ? fn_identity() : Fn{pa, pb, pc};
    Fn wexcl     = (wid  == 0) ? fn_identity() : warpTot[wid - 1];
    Fn excl = fn_compose(wexcl, lane_excl);

    // ---- exact sequential recurrence within this thread's SEG rows ----
    float c = fn_apply(excl, s_start);
    #pragma unroll
    for (int i = 0; i < SEG; i++) {
        c = fminf(fmaxf(c + dv[i], 0.f), CLAMP_HI);
        cnt[tid * (SEG + 1) + i] = c;
    }
    __syncthreads();

    // ---- two independent drain groups, double-buffered bulk-DMA ----
    int g      = tid >> 7;            // 0 or 1
    int local  = tid & (GROUP - 1);   // 0..127
    int barid  = 1 + g;               // named barriers 1 and 2
    float* gstage = stage + g * (GROUP * MAXO);
    uint32_t gstage_sa = smem_u32(gstage);
    size_t gbase = ((size_t)bid * PER_BLOCK + g * (PER_BLOCK / 2)) * (size_t)MAXO;

    #pragma unroll 1
    for (int it = 0; it < PER_BLOCK / 2 / GROUP; it++) {
        if (it > 0) {
            // prior DMA of this group must finish READING gstage
            if (local == 0)
                asm volatile("cp.async.bulk.wait_group.read 0;" ::: "memory");
            asm volatile("bar.sync %0, %1;" :: "r"(barid), "n"(GROUP) : "memory");
        }
        int r = g * (PER_BLOCK / 2) + it * GROUP + local;
        float cc  = cnt[(r >> 2) * (SEG + 1) + (r & 3)];
        int   k   = (int)ceilf(cc);
        float ec  = __expf(s * cc);
        float emc = __expf(-s * cc);
        float sum = ec * SufAn[k] + emc * PreAp[k];
        float inv = __fdividef(1.0f, sum);
        float eci = ec * inv, emci = emc * inv;
        #pragma unroll
        for (int j = 0; j < MAXO; j++)
            gstage[local * MAXO + j] = (j >= k) ? An[j] * eci : Ap[j] * emci;
        asm volatile("bar.sync %0, %1;" :: "r"(barid), "n"(GROUP) : "memory");

        if (local == 0) {
            float* gdst = out + gbase + (size_t)it * (GROUP * MAXO);
            asm volatile("fence.proxy.async.shared::cta;" ::: "memory");
            asm volatile(
                "cp.async.bulk.global.shared::cta.bulk_group [%0], [%1], %2;"
                :: "l"(gdst), "r"(gstage_sa), "n"(GROUP * MAXO * 4) : "memory");
            asm volatile("cp.async.bulk.commit_group;" ::: "memory");
        }
    }
    // all bulk writes complete before the kernel ends
    if (local == 0)
        asm volatile("cp.async.bulk.wait_group 0;" ::: "memory");
}

// ---------------------------------------------------------------------------
extern "C" void kernel_launch(void* const* d_in, const int* in_sizes, int n_in,
                              void* d_out, int out_size) {
    const int*   seq   = (const int*)  d_in[0];
    const float* delta = (const float*)d_in[1];
    const float* bias  = (const float*)d_in[2];
    const float* scale = (const float*)d_in[3];
    float* out = (float*)d_out;

    k1_block_totals<<<K1_BLOCKS, K1_THREADS>>>(seq, delta);

    cudaLaunchConfig_t cfg = {};
    cfg.gridDim  = dim3(NB, 1, 1);
    cfg.blockDim = dim3(NTHREADS, 1, 1);
    cudaLaunchAttribute attrs[1];
    attrs[0].id = cudaLaunchAttributeProgrammaticStreamSerialization;
    attrs[0].val.programmaticStreamSerializationAllowed = 1;
    cfg.attrs = attrs;
    cfg.numAttrs = 1;
    cudaLaunchKernelEx(&cfg, k3_output, seq, delta, bias, scale, out);
}

// round 16
// speedup vs baseline: 1.0329x; 1.0329x over previous
#include <cuda_runtime.h>
#include <math.h>
#include <cstdint>

#define T_LEN     1048576
#define MAXO      25
#define CLAMP_HI  24.0f
#define SEG       4
#define NTHREADS  256
#define NWARP     (NTHREADS/32)
#define PER_BLOCK (SEG*NTHREADS)       /* 1024 */
#define NB        (T_LEN/PER_BLOCK)    /* 1024 tiles */
#define K1_THREADS 512
#define K1_ELEMS   16
#define K1_BLOCKS  (T_LEN/(K1_THREADS*K1_ELEMS))        /* 128 */
#define TILES_PER_K1 ((K1_THREADS*K1_ELEMS)/PER_BLOCK)  /* 8 */
#define FPT       (NB/NTHREADS)        /* 4 fns per thread in global scan */
#define FULLM     0xffffffffu

struct Fn { float a, b, c; };

__device__ Fn g_blockF[NB];

__device__ __forceinline__ Fn fn_identity() { return Fn{0.f, -1e30f, 1e30f}; }

// f1 applied first, then f2:  (f2 o f1)(x) = min(max(x+a, b), c)
__device__ __forceinline__ Fn fn_compose(Fn f1, Fn f2) {
    Fn r;
    r.a = f1.a + f2.a;
    r.b = fmaxf(f1.b + f2.a, f2.b);
    r.c = fminf(fmaxf(f1.c + f2.a, f2.b), f2.c);
    return r;
}

__device__ __forceinline__ float fn_apply(Fn f, float x) {
    return fminf(fmaxf(x + f.a, f.b), f.c);
}

__device__ __forceinline__ Fn warp_incl_scan(Fn v, int lane) {
    #pragma unroll
    for (int off = 1; off < 32; off <<= 1) {
        float pa = __shfl_up_sync(FULLM, v.a, off);
        float pb = __shfl_up_sync(FULLM, v.b, off);
        float pc = __shfl_up_sync(FULLM, v.c, off);
        if (lane >= off) v = fn_compose(Fn{pa, pb, pc}, v);
    }
    return v;
}

__device__ __forceinline__ uint32_t smem_u32(const void* p) {
    uint32_t a;
    asm("{ .reg .u64 t; cvta.to.shared.u64 t, %1; cvt.u32.u64 %0, t; }"
        : "=r"(a) : "l"(p));
    return a;
}

// ---------------------------------------------------------------------------
// K1: 128 blocks x 512 threads, 16 elems/thread -> 8 tile functions per block
// ---------------------------------------------------------------------------
__global__ void __launch_bounds__(K1_THREADS)
k1_block_totals(const int* __restrict__ seq, const float* __restrict__ delta) {
    asm volatile("griddepcontrol.launch_dependents;" ::: "memory");

    __shared__ float dl[16];
    __shared__ Fn warpTot[K1_THREADS / 32];   // 16
    int tid = threadIdx.x, lane = tid & 31, wid = tid >> 5;
    if (tid < 16) dl[tid] = delta[tid];
    __syncthreads();

    const int4* p = (const int4*)(seq + (size_t)blockIdx.x * (K1_THREADS * K1_ELEMS)
                                      + tid * K1_ELEMS);
    int4 w0 = p[0], w1 = p[1], w2 = p[2], w3 = p[3];
    int vals[16] = {w0.x, w0.y, w0.z, w0.w, w1.x, w1.y, w1.z, w1.w,
                    w2.x, w2.y, w2.z, w2.w, w3.x, w3.y, w3.z, w3.w};

    Fn f = fn_identity();
    #pragma unroll
    for (int i = 0; i < 16; i++) {
        float d = dl[vals[i]];
        f.a += d;
        f.b = fmaxf(f.b + d, 0.f);
        f.c = fminf(fmaxf(f.c + d, 0.f), CLAMP_HI);
    }
    Fn inc = warp_incl_scan(f, lane);
    if (lane == 31) warpTot[wid] = inc;
    __syncthreads();
    if (tid < TILES_PER_K1) {
        Fn t = fn_compose(warpTot[tid * 2], warpTot[tid * 2 + 1]);
        g_blockF[blockIdx.x * TILES_PER_K1 + tid] = t;
    }
}

// ---------------------------------------------------------------------------
// K3: R14 structure verbatim (block-level bulk-DMA drain, scalar tables),
//     plus a PDL wait immediately before the g_blockF loads.
// ---------------------------------------------------------------------------
__global__ void __launch_bounds__(NTHREADS)
k3_output(const int* __restrict__ seq, const float* __restrict__ delta,
          const float* __restrict__ bias, const float* __restrict__ scale,
          float* __restrict__ out) {
    __shared__ float dl[16];
    __shared__ float An[MAXO], Ap[MAXO];
    __shared__ float SufAn[MAXO + 1], PreAp[MAXO + 1];
    __shared__ Fn    warpTotG[NWARP];
    __shared__ Fn    warpTot[NWARP];
    __shared__ float s_start;
    __shared__ __align__(16) float cnt[NTHREADS * (SEG + 1)];   // 5.1 KB
    __shared__ __align__(16) float stage[NTHREADS * MAXO];      // 25.6 KB

    int tid = threadIdx.x, lane = tid & 31, wid = tid >> 5, bid = blockIdx.x;
    float s = scale[0];
    if (tid < 16) dl[tid] = delta[tid];
    if (tid < MAXO) {
        float fj = (float)tid;
        An[tid] = expf(bias[tid] - s * fj);   // j >= c path (* e^{ s c})
        Ap[tid] = expf(bias[tid] + s * fj);   // j <  c path (* e^{-s c})
    }

    // issue seq loads early
    const int4* p = (const int4*)(seq + (size_t)bid * PER_BLOCK + tid * SEG);
    int4 v0 = p[0];

    // K1's g_blockF stores must be visible past this point (PDL)
    asm volatile("griddepcontrol.wait;" ::: "memory");

    // load this thread's FPT=4 global tile functions (L2-hot)
    Fn g4[FPT];
    #pragma unroll
    for (int i = 0; i < FPT; i++) g4[i] = g_blockF[FPT * tid + i];
    __syncthreads();

    if (tid == 0) {
        float a = 0.f;
        SufAn[MAXO] = 0.f;
        for (int k = MAXO - 1; k >= 0; k--) { a += An[k]; SufAn[k] = a; }
    }
    if (tid == 32) {
        float a = 0.f;
        PreAp[0] = 0.f;
        for (int k = 1; k <= MAXO; k++) { a += Ap[k - 1]; PreAp[k] = a; }
    }

    // ---- block-wide scan over the 1024 tile functions (4 per thread) ----
    Fn quad = g4[0];
    #pragma unroll
    for (int i = 1; i < FPT; i++) quad = fn_compose(quad, g4[i]);
    Fn incG = warp_incl_scan(quad, lane);
    if (lane == 31) warpTotG[wid] = incG;
    __syncthreads();
    if (wid == 0) {
        Fn v = (lane < NWARP) ? warpTotG[lane] : fn_identity();
        #pragma unroll
        for (int off = 1; off < NWARP; off <<= 1) {
            float pa = __shfl_up_sync(FULLM, v.a, off);
            float pb = __shfl_up_sync(FULLM, v.b, off);
            float pc = __shfl_up_sync(FULLM, v.c, off);
            if (lane >= off) v = fn_compose(Fn{pa, pb, pc}, v);
        }
        if (lane < NWARP) warpTotG[lane] = v;
    }
    __syncthreads();
    {
        float pa = __shfl_up_sync(FULLM, incG.a, 1);
        float pb = __shfl_up_sync(FULLM, incG.b, 1);
        float pc = __shfl_up_sync(FULLM, incG.c, 1);
        Fn lane_excl = (lane == 0) ? fn_identity() : Fn{pa, pb, pc};
        Fn wexcl     = (wid  == 0) ? fn_identity() : warpTotG[wid - 1];
        Fn exclG = fn_compose(wexcl, lane_excl);   // prefix of fns [0, FPT*tid)
        if (tid == (bid >> 2)) {
            Fn e = exclG;
            #pragma unroll
            for (int i = 0; i < FPT - 1; i++)
                if (i < (bid & 3)) e = fn_compose(e, g4[i]);
            s_start = fn_apply(e, 0.f);
        }
    }

    // ---- per-thread fn over its 4 symbols ----
    int vals[SEG] = {v0.x, v0.y, v0.z, v0.w};
    float dv[SEG];
    Fn f = fn_identity();
    #pragma unroll
    for (int i = 0; i < SEG; i++) {
        float d = dl[vals[i]];
        dv[i] = d;
        f.a += d;
        f.b = fmaxf(f.b + d, 0.f);
        f.c = fminf(fmaxf(f.c + d, 0.f), CLAMP_HI);
    }

    // ---- block scan of thread functions ----
    Fn inc = warp_incl_scan(f, lane);
    if (lane == 31) warpTot[wid] = inc;
    __syncthreads();                                // also publishes s_start
    if (wid == 0) {
        Fn v = (lane < NWARP) ? warpTot[lane] : fn_identity();
        #pragma unroll
        for (int off = 1; off < NWARP; off <<= 1) {
            float pa = __shfl_up_sync(FULLM, v.a, off);
            float pb = __shfl_up_sync(FULLM, v.b, off);
            float pc = __shfl_up_sync(FULLM, v.c, off);
            if (lane >= off) v = fn_compose(Fn{pa, pb, pc}, v);
        }
        if (lane < NWARP) warpTot[lane] = v;
    }
    __syncthreads();
    float pa = __shfl_up_sync(FULLM, inc.a, 1);
    float pb = __shfl_up_sync(FULLM, inc.b, 1);
    float pc = __shfl_up_sync(FULLM, inc.c, 1);
    Fn lane_excl = (lane == 0) ? fn_identity() : Fn{pa, pb, pc};
    Fn wexcl     = (wid  == 0) ? fn_identity() : warpTot[wid - 1];
    Fn excl = fn_compose(wexcl, lane_excl);

    // ---- exact sequential recurrence within this thread's SEG rows ----
    float c = fn_apply(excl, s_start);
    #pragma unroll
    for (int i = 0; i < SEG; i++) {
        c = fminf(fmaxf(c + dv[i], 0.f), CLAMP_HI);
        cnt[tid * (SEG + 1) + i] = c;
    }
    __syncthreads();

    // ---- softmax in 4 batches of 256 rows; block-level bulk-DMA drain ----
    uint32_t stage_sa = smem_u32(stage);

    #pragma unroll 1
    for (int batch = 0; batch < SEG; batch++) {
        if (batch > 0) {
            // prior DMA must finish READING stage before we overwrite it
            if (tid == 0)
                asm volatile("cp.async.bulk.wait_group.read 0;" ::: "memory");
            __syncthreads();
        }
        int r = batch * NTHREADS + tid;
        float cc  = cnt[(r >> 2) * (SEG + 1) + (r & 3)];
        int   k   = (int)ceilf(cc);
        float ec  = __expf(s * cc);
        float emc = __expf(-s * cc);
        float sum = ec * SufAn[k] + emc * PreAp[k];
        float inv = __fdividef(1.0f, sum);
        float eci = ec * inv, emci = emc * inv;
        #pragma unroll
        for (int j = 0; j < MAXO; j++)
            stage[tid * MAXO + j] = (j >= k) ? An[j] * eci : Ap[j] * emci;
        __syncthreads();

        if (tid == 0) {
            float* gdst = out + ((size_t)bid * PER_BLOCK + batch * NTHREADS) * (size_t)MAXO;
            asm volatile("fence.proxy.async.shared::cta;" ::: "memory");
            asm volatile(
                "cp.async.bulk.global.shared::cta.bulk_group [%0], [%1], %2;"
                :: "l"(gdst), "r"(stage_sa), "n"(NTHREADS * MAXO * 4) : "memory");
            asm volatile("cp.async.bulk.commit_group;" ::: "memory");
        }
    }
    // ensure all bulk writes are complete before the grid finishes
    if (tid == 0)
        asm volatile("cp.async.bulk.wait_group 0;" ::: "memory");
}

// ---------------------------------------------------------------------------
extern "C" void kernel_launch(void* const* d_in, const int* in_sizes, int n_in,
                              void* d_out, int out_size) {
    const int*   seq   = (const int*)  d_in[0];
    const float* delta = (const float*)d_in[1];
    const float* bias  = (const float*)d_in[2];
    const float* scale = (const float*)d_in[3];
    float* out = (float*)d_out;

    k1_block_totals<<<K1_BLOCKS, K1_THREADS>>>(seq, delta);

    cudaLaunchConfig_t cfg = {};
    cfg.gridDim  = dim3(NB, 1, 1);
    cfg.blockDim = dim3(NTHREADS, 1, 1);
    cudaLaunchAttribute attrs[1];
    attrs[0].id = cudaLaunchAttributeProgrammaticStreamSerialization;
    attrs[0].val.programmaticStreamSerializationAllowed = 1;
    cfg.attrs = attrs;
    cfg.numAttrs = 1;
    cudaLaunchKernelEx(&cfg, k3_output, seq, delta, bias, scale, out);
}